// round 1
// baseline (speedup 1.0000x reference)
#include <cuda_runtime.h>
#include <cstddef>

// Problem dims
#define Bv  4
#define Qv  1024
#define Kv  1024
#define Dv  256
#define Hv  64
#define DVv 256

// Scratch (allocation-free rule: __device__ globals)
__device__ float g_qp[Bv * Qv * Hv];                 // 1 MB
__device__ float g_kp[Bv * Kv * Hv];                 // 1 MB
__device__ float g_sc[(size_t)Bv * Qv * Kv];         // 16 MB

__device__ __forceinline__ float tanh_fast(float x) {
    float y;
    asm("tanh.approx.f32 %0, %1;" : "=f"(y) : "f"(x));
    return y;
}

// ---------------------------------------------------------------------------
// Generic fp32 tiled GEMM: C[M,N] = A[M,K] * B[K,N], row-major.
// BM=BN=64, BK=16, 256 threads, 4x4 per-thread microtile.
// blockIdx.z = batch, with per-batch element strides sA/sB/sC.
// Used for both the projections (N=64) and attn @ values (N=256).
// ---------------------------------------------------------------------------
__global__ __launch_bounds__(256)
void gemm64_kernel(const float* __restrict__ Ag, const float* __restrict__ Bg,
                   float* __restrict__ Cg, int K, int N,
                   size_t sA, size_t sB, size_t sC)
{
    const float* A = Ag + blockIdx.z * sA;
    const float* B = Bg + blockIdx.z * sB;
    float*       C = Cg + blockIdx.z * sC;

    __shared__ float As[64][16];   // contiguous rows: conflict-free STS.128 & broadcast LDS
    __shared__ float Bs[16][64];

    const int t    = threadIdx.x;      // 0..255
    const int trow = t >> 4;           // 0..15
    const int tcol = t & 15;           // 0..15
    const int m0 = blockIdx.y * 64;
    const int n0 = blockIdx.x * 64;

    const int a_row = t >> 2;          // 0..63
    const int a_k4  = (t & 3) << 2;    // 0,4,8,12
    const int b_k   = t >> 4;          // 0..15
    const int b_n4  = (t & 15) << 2;   // 0..60

    float acc[4][4];
#pragma unroll
    for (int i = 0; i < 4; i++)
#pragma unroll
        for (int j = 0; j < 4; j++) acc[i][j] = 0.f;

    for (int k0 = 0; k0 < K; k0 += 16) {
        float4 av = *(const float4*)(A + (size_t)(m0 + a_row) * K + k0 + a_k4);
        float4 bv = *(const float4*)(B + (size_t)(k0 + b_k) * N + n0 + b_n4);
        *(float4*)&As[a_row][a_k4] = av;
        *(float4*)&Bs[b_k][b_n4]   = bv;
        __syncthreads();

#pragma unroll
        for (int kk = 0; kk < 16; kk++) {
            float4 b4 = *(const float4*)&Bs[kk][tcol << 2];
            float a0 = As[(trow << 2) + 0][kk];
            float a1 = As[(trow << 2) + 1][kk];
            float a2 = As[(trow << 2) + 2][kk];
            float a3 = As[(trow << 2) + 3][kk];
            acc[0][0] += a0 * b4.x; acc[0][1] += a0 * b4.y; acc[0][2] += a0 * b4.z; acc[0][3] += a0 * b4.w;
            acc[1][0] += a1 * b4.x; acc[1][1] += a1 * b4.y; acc[1][2] += a1 * b4.z; acc[1][3] += a1 * b4.w;
            acc[2][0] += a2 * b4.x; acc[2][1] += a2 * b4.y; acc[2][2] += a2 * b4.z; acc[2][3] += a2 * b4.w;
            acc[3][0] += a3 * b4.x; acc[3][1] += a3 * b4.y; acc[3][2] += a3 * b4.z; acc[3][3] += a3 * b4.w;
        }
        __syncthreads();
    }

#pragma unroll
    for (int i = 0; i < 4; i++) {
        float4 o = make_float4(acc[i][0], acc[i][1], acc[i][2], acc[i][3]);
        *(float4*)(C + (size_t)(m0 + (trow << 2) + i) * N + n0 + (tcol << 2)) = o;
    }
}

// ---------------------------------------------------------------------------
// Scores: s[b,q,k] = sum_h w_v[h] * tanh(qp[b,q,h] + kp[b,k,h])
// Block tile: 32 q x 64 k. 256 threads: tx=k-slot (0..31, +32), ty*4+i = q.
// MUFU.TANH-bound by design; LDS laid out conflict-free (kp padded to 65).
// ---------------------------------------------------------------------------
__global__ __launch_bounds__(256)
void scores_kernel(const float* __restrict__ wv_g)
{
    __shared__ float s_qp[32][64];
    __shared__ float s_kp[64][65];
    __shared__ float s_wv[64];

    const int t  = threadIdx.x;
    const int b  = blockIdx.z;
    const int q0 = blockIdx.y * 32;
    const int k0 = blockIdx.x * 64;

    const float* qp = g_qp + ((size_t)b * Qv + q0) * Hv;
    const float* kp = g_kp + ((size_t)b * Kv + k0) * Hv;

#pragma unroll
    for (int i = t; i < 32 * 64; i += 256) s_qp[i >> 6][i & 63] = qp[i];
#pragma unroll
    for (int i = t; i < 64 * 64; i += 256) s_kp[i >> 6][i & 63] = kp[i];
    if (t < 64) s_wv[t] = wv_g[t];
    __syncthreads();

    const int tx = t & 31;
    const int ty = t >> 5;

    float acc[4][2] = {};
#pragma unroll 8
    for (int h = 0; h < 64; h++) {
        float w   = s_wv[h];
        float kv0 = s_kp[tx][h];
        float kv1 = s_kp[tx + 32][h];
#pragma unroll
        for (int i = 0; i < 4; i++) {
            float qv = s_qp[(ty << 2) + i][h];
            acc[i][0] += w * tanh_fast(qv + kv0);
            acc[i][1] += w * tanh_fast(qv + kv1);
        }
    }

    float* out = g_sc + ((size_t)b * Qv + q0) * Kv + k0;
#pragma unroll
    for (int i = 0; i < 4; i++) {
        int q = (ty << 2) + i;
        out[(size_t)q * Kv + tx]      = acc[i][0];
        out[(size_t)q * Kv + tx + 32] = acc[i][1];
    }
}

// ---------------------------------------------------------------------------
// Row softmax over K=1024, in-place on g_sc. One block per (b,q) row.
// ---------------------------------------------------------------------------
__global__ __launch_bounds__(256)
void softmax_kernel()
{
    float* p = g_sc + (size_t)blockIdx.x * 1024;
    const int t = threadIdx.x;

    float4 v = *(float4*)(p + (t << 2));
    float m = fmaxf(fmaxf(v.x, v.y), fmaxf(v.z, v.w));
#pragma unroll
    for (int o = 16; o; o >>= 1) m = fmaxf(m, __shfl_xor_sync(~0u, m, o));

    __shared__ float redm[8];
    __shared__ float reds[8];
    if ((t & 31) == 0) redm[t >> 5] = m;
    __syncthreads();
    float mall = redm[0];
#pragma unroll
    for (int w = 1; w < 8; w++) mall = fmaxf(mall, redm[w]);

    float e0 = __expf(v.x - mall);
    float e1 = __expf(v.y - mall);
    float e2 = __expf(v.z - mall);
    float e3 = __expf(v.w - mall);
    float s = e0 + e1 + e2 + e3;
#pragma unroll
    for (int o = 16; o; o >>= 1) s += __shfl_xor_sync(~0u, s, o);
    if ((t & 31) == 0) reds[t >> 5] = s;
    __syncthreads();
    float stot = reds[0];
#pragma unroll
    for (int w = 1; w < 8; w++) stot += reds[w];

    float inv = 1.0f / stot;
    v.x = e0 * inv; v.y = e1 * inv; v.z = e2 * inv; v.w = e3 * inv;
    *(float4*)(p + (t << 2)) = v;
}

// ---------------------------------------------------------------------------
// kernel_launch: 5 graph-capturable launches, no allocation, default stream.
// ---------------------------------------------------------------------------
extern "C" void kernel_launch(void* const* d_in, const int* in_sizes, int n_in,
                              void* d_out, int out_size)
{
    (void)in_sizes; (void)n_in; (void)out_size;
    const float* queries = (const float*)d_in[0];
    const float* keys    = (const float*)d_in[1];
    const float* values  = (const float*)d_in[2];
    const float* W_q     = (const float*)d_in[3];
    const float* W_k     = (const float*)d_in[4];
    const float* w_v     = (const float*)d_in[5];
    float* out = (float*)d_out;

    float *qp, *kp, *sc;
    cudaGetSymbolAddress((void**)&qp, g_qp);
    cudaGetSymbolAddress((void**)&kp, g_kp);
    cudaGetSymbolAddress((void**)&sc, g_sc);

    // 1-2. projections: [4096,256] @ [256,64] -> [4096,64]
    gemm64_kernel<<<dim3(1, (Bv * Qv) / 64, 1), 256>>>(queries, W_q, qp, Dv, Hv, 0, 0, 0);
    gemm64_kernel<<<dim3(1, (Bv * Kv) / 64, 1), 256>>>(keys,    W_k, kp, Dv, Hv, 0, 0, 0);

    // 3. additive-tanh scores -> g_sc
    scores_kernel<<<dim3(Kv / 64, Qv / 32, Bv), 256>>>(w_v);

    // 4. softmax over K, in-place
    softmax_kernel<<<Bv * Qv, 256>>>();

    // 5. out = attn @ values : per batch [1024,1024] @ [1024,256]
    gemm64_kernel<<<dim3(DVv / 64, Qv / 64, Bv), 256>>>(
        sc, values, out, Kv, DVv,
        (size_t)Qv * Kv, (size_t)Kv * DVv, (size_t)Qv * DVv);
}

// round 2
// speedup vs baseline: 1.3533x; 1.3533x over previous
#include <cuda_runtime.h>
#include <cuda_bf16.h>
#include <cstdint>
#include <cstddef>

// Problem dims
#define Bv  4
#define Qv  1024
#define Kv  1024
#define Dv  256
#define Hv  64
#define DVv 256

// Scratch (allocation-free rule: __device__ globals)
__device__ __align__(16) float g_qp[Bv * Qv * Hv];                 // 1 MB
__device__ __align__(16) float g_kp[Bv * Kv * Hv];                 // 1 MB
__device__ __align__(16) float g_sc[(size_t)Bv * Qv * Kv];         // 16 MB
__device__ __align__(16) __nv_bfloat16 g_ahi[(size_t)Bv * Qv * Kv];   // 8 MB
__device__ __align__(16) __nv_bfloat16 g_alo[(size_t)Bv * Qv * Kv];   // 8 MB
__device__ __align__(16) __nv_bfloat16 g_vhi[Bv * Kv * DVv];          // 2 MB
__device__ __align__(16) __nv_bfloat16 g_vlo[Bv * Kv * DVv];          // 2 MB

__device__ __forceinline__ float tanh_fast(float x) {
    float y;
    asm("tanh.approx.f32 %0, %1;" : "=f"(y) : "f"(x));
    return y;
}

__device__ __forceinline__ uint32_t s2u(const void* p) {
    uint32_t a;
    asm("{ .reg .u64 t; cvta.to.shared.u64 t, %1; cvt.u32.u64 %0, t; }" : "=r"(a) : "l"(p));
    return a;
}

__device__ __forceinline__ void cp16(uint32_t dst, const void* src) {
    asm volatile("cp.async.cg.shared.global [%0], [%1], 16;" :: "r"(dst), "l"(src));
}
__device__ __forceinline__ void cp_commit() { asm volatile("cp.async.commit_group;"); }
template <int N> __device__ __forceinline__ void cp_wait() {
    asm volatile("cp.async.wait_group %0;" :: "n"(N));
}

__device__ __forceinline__ void ldsm4(uint32_t* r, uint32_t addr) {
    asm volatile("ldmatrix.sync.aligned.m8n8.x4.shared.b16 {%0,%1,%2,%3}, [%4];"
                 : "=r"(r[0]), "=r"(r[1]), "=r"(r[2]), "=r"(r[3]) : "r"(addr));
}
__device__ __forceinline__ void ldsm4t(uint32_t* r, uint32_t addr) {
    asm volatile("ldmatrix.sync.aligned.m8n8.x4.trans.shared.b16 {%0,%1,%2,%3}, [%4];"
                 : "=r"(r[0]), "=r"(r[1]), "=r"(r[2]), "=r"(r[3]) : "r"(addr));
}
__device__ __forceinline__ void mma_bf16(float* d, const uint32_t* a, const uint32_t* b) {
    asm volatile(
        "mma.sync.aligned.m16n8k16.row.col.f32.bf16.bf16.f32 "
        "{%0,%1,%2,%3},{%4,%5,%6,%7},{%8,%9},{%0,%1,%2,%3};"
        : "+f"(d[0]), "+f"(d[1]), "+f"(d[2]), "+f"(d[3])
        : "r"(a[0]), "r"(a[1]), "r"(a[2]), "r"(a[3]), "r"(b[0]), "r"(b[1]));
}

// ---------------------------------------------------------------------------
// Fused projections: qp = queries@W_q, kp = keys@W_k.
// grid (1, 128): by<64 -> queries block, else keys block. K=256, N=64.
// ---------------------------------------------------------------------------
__global__ __launch_bounds__(256)
void proj_kernel(const float* __restrict__ Qg, const float* __restrict__ Kg,
                 const float* __restrict__ Wq, const float* __restrict__ Wk)
{
    const bool isQ = blockIdx.y < 64;
    const float* A = (isQ ? Qg : Kg) + (size_t)(blockIdx.y & 63) * 64 * 256;
    const float* B = isQ ? Wq : Wk;
    float*       C = (isQ ? g_qp : g_kp) + (size_t)(blockIdx.y & 63) * 64 * 64;

    __shared__ float As[64][16];
    __shared__ float Bs[16][64];

    const int t    = threadIdx.x;
    const int trow = t >> 4;
    const int tcol = t & 15;
    const int a_row = t >> 2;
    const int a_k4  = (t & 3) << 2;
    const int b_k   = t >> 4;
    const int b_n4  = (t & 15) << 2;

    float acc[4][4] = {};

    for (int k0 = 0; k0 < 256; k0 += 16) {
        float4 av = *(const float4*)(A + (size_t)a_row * 256 + k0 + a_k4);
        float4 bv = *(const float4*)(B + (size_t)(k0 + b_k) * 64 + b_n4);
        *(float4*)&As[a_row][a_k4] = av;
        *(float4*)&Bs[b_k][b_n4]   = bv;
        __syncthreads();
#pragma unroll
        for (int kk = 0; kk < 16; kk++) {
            float4 b4 = *(const float4*)&Bs[kk][tcol << 2];
            float a0 = As[(trow << 2) + 0][kk];
            float a1 = As[(trow << 2) + 1][kk];
            float a2 = As[(trow << 2) + 2][kk];
            float a3 = As[(trow << 2) + 3][kk];
            acc[0][0] += a0 * b4.x; acc[0][1] += a0 * b4.y; acc[0][2] += a0 * b4.z; acc[0][3] += a0 * b4.w;
            acc[1][0] += a1 * b4.x; acc[1][1] += a1 * b4.y; acc[1][2] += a1 * b4.z; acc[1][3] += a1 * b4.w;
            acc[2][0] += a2 * b4.x; acc[2][1] += a2 * b4.y; acc[2][2] += a2 * b4.z; acc[2][3] += a2 * b4.w;
            acc[3][0] += a3 * b4.x; acc[3][1] += a3 * b4.y; acc[3][2] += a3 * b4.z; acc[3][3] += a3 * b4.w;
        }
        __syncthreads();
    }
#pragma unroll
    for (int i = 0; i < 4; i++) {
        float4 o = make_float4(acc[i][0], acc[i][1], acc[i][2], acc[i][3]);
        *(float4*)(C + (size_t)((trow << 2) + i) * 64 + (tcol << 2)) = o;
    }
}

// ---------------------------------------------------------------------------
// Scores: s[b,q,k] = sum_h w_v[h] * tanh(qp[b,q,h] + kp[b,k,h])   (MUFU floor)
// ---------------------------------------------------------------------------
__global__ __launch_bounds__(256)
void scores_kernel(const float* __restrict__ wv_g)
{
    __shared__ float s_qp[32][64];
    __shared__ float s_kp[64][65];
    __shared__ float s_wv[64];

    const int t  = threadIdx.x;
    const int b  = blockIdx.z;
    const int q0 = blockIdx.y * 32;
    const int k0 = blockIdx.x * 64;

    const float* qp = g_qp + ((size_t)b * Qv + q0) * Hv;
    const float* kp = g_kp + ((size_t)b * Kv + k0) * Hv;

    for (int i = t; i < 32 * 64; i += 256) s_qp[i >> 6][i & 63] = qp[i];
    for (int i = t; i < 64 * 64; i += 256) s_kp[i >> 6][i & 63] = kp[i];
    if (t < 64) s_wv[t] = wv_g[t];
    __syncthreads();

    const int tx = t & 31;
    const int ty = t >> 5;

    float acc[4][2] = {};
#pragma unroll 8
    for (int h = 0; h < 64; h++) {
        float w   = s_wv[h];
        float kv0 = s_kp[tx][h];
        float kv1 = s_kp[tx + 32][h];
#pragma unroll
        for (int i = 0; i < 4; i++) {
            float qv = s_qp[(ty << 2) + i][h];
            acc[i][0] += w * tanh_fast(qv + kv0);
            acc[i][1] += w * tanh_fast(qv + kv1);
        }
    }

    float* out = g_sc + ((size_t)b * Qv + q0) * Kv + k0;
#pragma unroll
    for (int i = 0; i < 4; i++) {
        int q = (ty << 2) + i;
        out[(size_t)q * Kv + tx]      = acc[i][0];
        out[(size_t)q * Kv + tx + 32] = acc[i][1];
    }
}

// ---------------------------------------------------------------------------
// Row softmax over K=1024; emits attn as bf16 hi/lo planes (bf16x2 split).
// ---------------------------------------------------------------------------
__global__ __launch_bounds__(256)
void softmax_kernel()
{
    const size_t row = (size_t)blockIdx.x * 1024;
    float* p = g_sc + row;
    const int t = threadIdx.x;

    float4 v = *(float4*)(p + (t << 2));
    float m = fmaxf(fmaxf(v.x, v.y), fmaxf(v.z, v.w));
#pragma unroll
    for (int o = 16; o; o >>= 1) m = fmaxf(m, __shfl_xor_sync(~0u, m, o));

    __shared__ float redm[8];
    __shared__ float reds[8];
    if ((t & 31) == 0) redm[t >> 5] = m;
    __syncthreads();
    float mall = redm[0];
#pragma unroll
    for (int w = 1; w < 8; w++) mall = fmaxf(mall, redm[w]);

    float e0 = __expf(v.x - mall);
    float e1 = __expf(v.y - mall);
    float e2 = __expf(v.z - mall);
    float e3 = __expf(v.w - mall);
    float s = e0 + e1 + e2 + e3;
#pragma unroll
    for (int o = 16; o; o >>= 1) s += __shfl_xor_sync(~0u, s, o);
    if ((t & 31) == 0) reds[t >> 5] = s;
    __syncthreads();
    float stot = reds[0];
#pragma unroll
    for (int w = 1; w < 8; w++) stot += reds[w];

    float inv = 1.0f / stot;
    float a0 = e0 * inv, a1 = e1 * inv, a2 = e2 * inv, a3 = e3 * inv;

    __nv_bfloat16 h0 = __float2bfloat16(a0), h1 = __float2bfloat16(a1);
    __nv_bfloat16 h2 = __float2bfloat16(a2), h3 = __float2bfloat16(a3);
    __nv_bfloat16 l0 = __float2bfloat16(a0 - __bfloat162float(h0));
    __nv_bfloat16 l1 = __float2bfloat16(a1 - __bfloat162float(h1));
    __nv_bfloat16 l2 = __float2bfloat16(a2 - __bfloat162float(h2));
    __nv_bfloat16 l3 = __float2bfloat16(a3 - __bfloat162float(h3));

    ushort4 hp = make_ushort4(*(uint16_t*)&h0, *(uint16_t*)&h1, *(uint16_t*)&h2, *(uint16_t*)&h3);
    ushort4 lp = make_ushort4(*(uint16_t*)&l0, *(uint16_t*)&l1, *(uint16_t*)&l2, *(uint16_t*)&l3);
    *(ushort4*)(g_ahi + row + (t << 2)) = hp;
    *(ushort4*)(g_alo + row + (t << 2)) = lp;
}

// ---------------------------------------------------------------------------
// Split values into bf16 hi/lo planes.
// ---------------------------------------------------------------------------
__global__ __launch_bounds__(256)
void vsplit_kernel(const float* __restrict__ V)
{
    size_t i = ((size_t)blockIdx.x * 256 + threadIdx.x) * 4;
    float4 v = *(const float4*)(V + i);
    __nv_bfloat16 h0 = __float2bfloat16(v.x), h1 = __float2bfloat16(v.y);
    __nv_bfloat16 h2 = __float2bfloat16(v.z), h3 = __float2bfloat16(v.w);
    __nv_bfloat16 l0 = __float2bfloat16(v.x - __bfloat162float(h0));
    __nv_bfloat16 l1 = __float2bfloat16(v.y - __bfloat162float(h1));
    __nv_bfloat16 l2 = __float2bfloat16(v.z - __bfloat162float(h2));
    __nv_bfloat16 l3 = __float2bfloat16(v.w - __bfloat162float(h3));
    *(ushort4*)(g_vhi + i) = make_ushort4(*(uint16_t*)&h0, *(uint16_t*)&h1, *(uint16_t*)&h2, *(uint16_t*)&h3);
    *(ushort4*)(g_vlo + i) = make_ushort4(*(uint16_t*)&l0, *(uint16_t*)&l1, *(uint16_t*)&l2, *(uint16_t*)&l3);
}

// ---------------------------------------------------------------------------
// AV GEMM: out[b] = attn[b] @ values[b], bf16x3 HMMA (m16n8k16).
// CTA tile 64(M) x 128(N), K-step 32, 4 warps (each 64x32), cp.async dbl-buf.
// grid (2, 16, 4), 128 threads, 55296 B dynamic smem.
// ---------------------------------------------------------------------------
#define AS_ROW 40      // A smem row stride (bf16 elems), conflict-free LDSM
#define BS_ROW 136     // B smem row stride
#define A_PLANE (64 * AS_ROW)          // 2560 elems
#define B_PLANE (32 * BS_ROW)          // 4352 elems
#define SMEM_A_BYTES (2 * 2 * A_PLANE * 2)   // 20480
#define SMEM_B_BYTES (2 * 2 * B_PLANE * 2)   // 34816
#define SMEM_TOTAL_AV (SMEM_A_BYTES + SMEM_B_BYTES)

__global__ __launch_bounds__(128)
void av_mma_kernel(float* __restrict__ Out)
{
    extern __shared__ char dyn[];
    const uint32_t sA = s2u(dyn);
    const uint32_t sB = s2u(dyn + SMEM_A_BYTES);

    const int t = threadIdx.x, wid = t >> 5, lane = t & 31;
    const int b = blockIdx.z;
    const int m0 = blockIdx.y * 64;
    const int n0 = blockIdx.x * 128;

    const __nv_bfloat16* Ah = g_ahi + ((size_t)b * 1024 + m0) * 1024;
    const __nv_bfloat16* Al = g_alo + ((size_t)b * 1024 + m0) * 1024;
    const __nv_bfloat16* Vh = g_vhi + (size_t)b * 1024 * 256 + n0;
    const __nv_bfloat16* Vl = g_vlo + (size_t)b * 1024 * 256 + n0;

    // cp.async staging indices
    const int a_row = t >> 1, a_col = (t & 1) * 16;   // A tile [64][32]
    const int b_row = t >> 2, b_col = (t & 3) * 32;   // B tile [32][128]

    // ldmatrix lane offsets
    const int sub = lane >> 3, r8 = lane & 7;
    const uint32_t a_lane_off = (uint32_t)(((sub & 1) * 8 + r8) * (AS_ROW * 2) + (sub >> 1) * 16);
    const uint32_t b_lane_off = (uint32_t)(((sub & 1) * 8 + r8) * (BS_ROW * 2) + (sub >> 1) * 16);

    auto issue = [&](int step, int buf) {
        const size_t kb = (size_t)step * 32;
#pragma unroll
        for (int pl = 0; pl < 2; pl++) {
            const __nv_bfloat16* src = (pl ? Al : Ah) + (size_t)a_row * 1024 + kb + a_col;
            uint32_t d = sA + ((buf * 2 + pl) * A_PLANE + a_row * AS_ROW + a_col) * 2;
            cp16(d, src);
            cp16(d + 16, src + 8);
        }
#pragma unroll
        for (int pl = 0; pl < 2; pl++) {
            const __nv_bfloat16* src = (pl ? Vl : Vh) + (kb + b_row) * 256 + b_col;
            uint32_t d = sB + ((buf * 2 + pl) * B_PLANE + b_row * BS_ROW + b_col) * 2;
#pragma unroll
            for (int i = 0; i < 4; i++) cp16(d + 16 * i, src + 8 * i);
        }
    };

    float acc[4][4][4] = {};   // [mt][nt][4]

    issue(0, 0);
    cp_commit();

    for (int s = 0; s < 32; s++) {
        const int buf = s & 1;
        if (s < 31) { issue(s + 1, buf ^ 1); cp_commit(); cp_wait<1>(); }
        else        { cp_wait<0>(); }
        __syncthreads();

#pragma unroll
        for (int k0 = 0; k0 < 32; k0 += 16) {
            uint32_t Af[2][4][4];
#pragma unroll
            for (int pl = 0; pl < 2; pl++)
#pragma unroll
                for (int mt = 0; mt < 4; mt++) {
                    uint32_t addr = sA + ((buf * 2 + pl) * A_PLANE + mt * 16 * AS_ROW + k0) * 2 + a_lane_off;
                    ldsm4(Af[pl][mt], addr);
                }
            uint32_t Bf[2][4][2];
#pragma unroll
            for (int pl = 0; pl < 2; pl++)
#pragma unroll
                for (int ntp = 0; ntp < 2; ntp++) {
                    uint32_t rr[4];
                    uint32_t addr = sB + ((buf * 2 + pl) * B_PLANE + k0 * BS_ROW) * 2
                                  + (uint32_t)(wid * 64 + ntp * 32) + b_lane_off;
                    ldsm4t(rr, addr);
                    Bf[pl][ntp * 2][0] = rr[0]; Bf[pl][ntp * 2][1] = rr[1];
                    Bf[pl][ntp * 2 + 1][0] = rr[2]; Bf[pl][ntp * 2 + 1][1] = rr[3];
                }
#pragma unroll
            for (int mt = 0; mt < 4; mt++)
#pragma unroll
                for (int nt = 0; nt < 4; nt++) {
                    mma_bf16(acc[mt][nt], Af[0][mt], Bf[0][nt]);  // hi*hi
                    mma_bf16(acc[mt][nt], Af[0][mt], Bf[1][nt]);  // hi*lo
                    mma_bf16(acc[mt][nt], Af[1][mt], Bf[0][nt]);  // lo*hi
                }
        }
        __syncthreads();
    }

    // epilogue
    const int g  = lane >> 2;
    const int tq = lane & 3;
    float* Ob = Out + (size_t)b * 1024 * 256;
#pragma unroll
    for (int mt = 0; mt < 4; mt++)
#pragma unroll
        for (int nt = 0; nt < 4; nt++) {
            int row = m0 + mt * 16 + g;
            int col = n0 + wid * 32 + nt * 8 + tq * 2;
            *(float2*)(Ob + (size_t)row * 256 + col)       = make_float2(acc[mt][nt][0], acc[mt][nt][1]);
            *(float2*)(Ob + (size_t)(row + 8) * 256 + col) = make_float2(acc[mt][nt][2], acc[mt][nt][3]);
        }
}

// ---------------------------------------------------------------------------
extern "C" void kernel_launch(void* const* d_in, const int* in_sizes, int n_in,
                              void* d_out, int out_size)
{
    (void)in_sizes; (void)n_in; (void)out_size;
    const float* queries = (const float*)d_in[0];
    const float* keys    = (const float*)d_in[1];
    const float* values  = (const float*)d_in[2];
    const float* W_q     = (const float*)d_in[3];
    const float* W_k     = (const float*)d_in[4];
    const float* w_v     = (const float*)d_in[5];
    float* out = (float*)d_out;

    cudaFuncSetAttribute(av_mma_kernel, cudaFuncAttributeMaxDynamicSharedMemorySize, SMEM_TOTAL_AV);

    // 1. fused projections
    proj_kernel<<<dim3(1, 128, 1), 256>>>(queries, keys, W_q, W_k);

    // 2. additive-tanh scores
    scores_kernel<<<dim3(Kv / 64, Qv / 32, Bv), 256>>>(w_v);

    // 3. softmax -> bf16 hi/lo attn planes
    softmax_kernel<<<Bv * Qv, 256>>>();

    // 4. split values into bf16 hi/lo planes (independent of 1-3)
    vsplit_kernel<<<(Bv * Kv * DVv) / (256 * 4), 256>>>(values);

    // 5. out = attn @ values via bf16x3 HMMA
    av_mma_kernel<<<dim3(DVv / 128, Qv / 64, Bv), 128, SMEM_TOTAL_AV>>>(out);
}

// round 5
// speedup vs baseline: 1.4191x; 1.0486x over previous
#include <cuda_runtime.h>
#include <cuda_bf16.h>
#include <cuda_fp16.h>
#include <cstdint>
#include <cstddef>

// Problem dims
#define Bv  4
#define Qv  1024
#define Kv  1024
#define Dv  256
#define Hv  64
#define DVv 256

// Scratch (allocation-free rule: __device__ globals)
__device__ __align__(16) __half g_qp[Bv * Qv * Hv];                   // 512 KB (f16)
__device__ __align__(16) __half g_kp[Bv * Kv * Hv];                   // 512 KB
__device__ __align__(16) float g_sc[(size_t)Bv * Qv * Kv];            // 16 MB
__device__ __align__(16) __nv_bfloat16 g_ahi[(size_t)Bv * Qv * Kv];   // 8 MB
__device__ __align__(16) __nv_bfloat16 g_alo[(size_t)Bv * Qv * Kv];   // 8 MB
__device__ __align__(16) __nv_bfloat16 g_vhi[Bv * Kv * DVv];          // 2 MB
__device__ __align__(16) __nv_bfloat16 g_vlo[Bv * Kv * DVv];          // 2 MB

__device__ __forceinline__ uint32_t tanh2(uint32_t x) {
    uint32_t y;
    asm("tanh.approx.f16x2 %0, %1;" : "=r"(y) : "r"(x));
    return y;
}

__device__ __forceinline__ uint32_t s2u(const void* p) {
    uint32_t a;
    asm("{ .reg .u64 t; cvta.to.shared.u64 t, %1; cvt.u32.u64 %0, t; }" : "=r"(a) : "l"(p));
    return a;
}

__device__ __forceinline__ void cp16(uint32_t dst, const void* src) {
    asm volatile("cp.async.cg.shared.global [%0], [%1], 16;" :: "r"(dst), "l"(src));
}
__device__ __forceinline__ void cp_commit() { asm volatile("cp.async.commit_group;"); }
template <int N> __device__ __forceinline__ void cp_wait() {
    asm volatile("cp.async.wait_group %0;" :: "n"(N));
}

__device__ __forceinline__ void ldsm4(uint32_t* r, uint32_t addr) {
    asm volatile("ldmatrix.sync.aligned.m8n8.x4.shared.b16 {%0,%1,%2,%3}, [%4];"
                 : "=r"(r[0]), "=r"(r[1]), "=r"(r[2]), "=r"(r[3]) : "r"(addr));
}
__device__ __forceinline__ void ldsm4t(uint32_t* r, uint32_t addr) {
    asm volatile("ldmatrix.sync.aligned.m8n8.x4.trans.shared.b16 {%0,%1,%2,%3}, [%4];"
                 : "=r"(r[0]), "=r"(r[1]), "=r"(r[2]), "=r"(r[3]) : "r"(addr));
}
__device__ __forceinline__ void mma_bf16(float* d, const uint32_t* a, const uint32_t* b) {
    asm volatile(
        "mma.sync.aligned.m16n8k16.row.col.f32.bf16.bf16.f32 "
        "{%0,%1,%2,%3},{%4,%5,%6,%7},{%8,%9},{%0,%1,%2,%3};"
        : "+f"(d[0]), "+f"(d[1]), "+f"(d[2]), "+f"(d[3])
        : "r"(a[0]), "r"(a[1]), "r"(a[2]), "r"(a[3]), "r"(b[0]), "r"(b[1]));
}

// ---------------------------------------------------------------------------
// Fused: projections (f16 output) + values bf16 hi/lo split, one launch.
// grid (1, 256): y<64 queries proj, y<128 keys proj, y>=128 vsplit strips.
// vsplit: 262144 float4 units total / (128 blocks * 256 thr) = 8 per thread.
// ---------------------------------------------------------------------------
__global__ __launch_bounds__(256)
void proj_vsplit_kernel(const float* __restrict__ Qg, const float* __restrict__ Kg,
                        const float* __restrict__ Wq, const float* __restrict__ Wk,
                        const float* __restrict__ Vg)
{
    if (blockIdx.y >= 128) {
        const int blk = blockIdx.y - 128;          // 0..127
#pragma unroll
        for (int it = 0; it < 8; it++) {
            size_t idx4 = (size_t)blk * 256 + threadIdx.x + (size_t)it * 32768; // float4 units
            size_t i = idx4 * 4;                   // element index, max 1048572
            float4 v = *(const float4*)(Vg + i);
            __nv_bfloat16 h0 = __float2bfloat16(v.x), h1 = __float2bfloat16(v.y);
            __nv_bfloat16 h2 = __float2bfloat16(v.z), h3 = __float2bfloat16(v.w);
            __nv_bfloat16 l0 = __float2bfloat16(v.x - __bfloat162float(h0));
            __nv_bfloat16 l1 = __float2bfloat16(v.y - __bfloat162float(h1));
            __nv_bfloat16 l2 = __float2bfloat16(v.z - __bfloat162float(h2));
            __nv_bfloat16 l3 = __float2bfloat16(v.w - __bfloat162float(h3));
            *(ushort4*)(g_vhi + i) = make_ushort4(*(uint16_t*)&h0, *(uint16_t*)&h1, *(uint16_t*)&h2, *(uint16_t*)&h3);
            *(ushort4*)(g_vlo + i) = make_ushort4(*(uint16_t*)&l0, *(uint16_t*)&l1, *(uint16_t*)&l2, *(uint16_t*)&l3);
        }
        return;
    }

    const bool isQ = blockIdx.y < 64;
    const float* A = (isQ ? Qg : Kg) + (size_t)(blockIdx.y & 63) * 64 * 256;
    const float* B = isQ ? Wq : Wk;
    __half*      C = (isQ ? g_qp : g_kp) + (size_t)(blockIdx.y & 63) * 64 * 64;

    __shared__ float As[64][16];
    __shared__ float Bs[16][64];

    const int t    = threadIdx.x;
    const int trow = t >> 4;
    const int tcol = t & 15;
    const int a_row = t >> 2;
    const int a_k4  = (t & 3) << 2;
    const int b_k   = t >> 4;
    const int b_n4  = (t & 15) << 2;

    float acc[4][4] = {};

    for (int k0 = 0; k0 < 256; k0 += 16) {
        float4 av = *(const float4*)(A + (size_t)a_row * 256 + k0 + a_k4);
        float4 bv = *(const float4*)(B + (size_t)(k0 + b_k) * 64 + b_n4);
        *(float4*)&As[a_row][a_k4] = av;
        *(float4*)&Bs[b_k][b_n4]   = bv;
        __syncthreads();
#pragma unroll
        for (int kk = 0; kk < 16; kk++) {
            float4 b4 = *(const float4*)&Bs[kk][tcol << 2];
            float a0 = As[(trow << 2) + 0][kk];
            float a1 = As[(trow << 2) + 1][kk];
            float a2 = As[(trow << 2) + 2][kk];
            float a3 = As[(trow << 2) + 3][kk];
            acc[0][0] += a0 * b4.x; acc[0][1] += a0 * b4.y; acc[0][2] += a0 * b4.z; acc[0][3] += a0 * b4.w;
            acc[1][0] += a1 * b4.x; acc[1][1] += a1 * b4.y; acc[1][2] += a1 * b4.z; acc[1][3] += a1 * b4.w;
            acc[2][0] += a2 * b4.x; acc[2][1] += a2 * b4.y; acc[2][2] += a2 * b4.z; acc[2][3] += a2 * b4.w;
            acc[3][0] += a3 * b4.x; acc[3][1] += a3 * b4.y; acc[3][2] += a3 * b4.z; acc[3][3] += a3 * b4.w;
        }
        __syncthreads();
    }
#pragma unroll
    for (int i = 0; i < 4; i++) {
        __half2 h01 = __floats2half2_rn(acc[i][0], acc[i][1]);
        __half2 h23 = __floats2half2_rn(acc[i][2], acc[i][3]);
        uint2 pk = make_uint2(*(uint32_t*)&h01, *(uint32_t*)&h23);
        *(uint2*)(C + (size_t)((trow << 2) + i) * 64 + (tcol << 2)) = pk;
    }
}

// ---------------------------------------------------------------------------
// Scores: s[b,q,k] = sum_h w_v[h] * tanh(qp+kp), f16x2 tanh (2 per MUFU op).
// Tile 32q x 64k, 256 threads; acc in f16x2, flushed to f32 every 4 h-pairs.
// ---------------------------------------------------------------------------
__global__ __launch_bounds__(256)
void scores_kernel(const float* __restrict__ wv_g)
{
    __shared__ __half2 s_qp[32][33];   // [q][h-pair]
    __shared__ __half2 s_kp[64][33];   // [k][h-pair], pad kills lane-stride conflicts
    __shared__ __half2 s_wv[32];

    const int t  = threadIdx.x;
    const int b  = blockIdx.z;
    const int q0 = blockIdx.y * 32;
    const int k0 = blockIdx.x * 64;

    const __half2* qp = (const __half2*)(g_qp + ((size_t)b * Qv + q0) * Hv);
    const __half2* kp = (const __half2*)(g_kp + ((size_t)b * Kv + k0) * Hv);

    for (int i = t; i < 32 * 32; i += 256) s_qp[i >> 5][i & 31] = qp[i];
    for (int i = t; i < 64 * 32; i += 256) s_kp[i >> 5][i & 31] = kp[i];
    if (t < 32) s_wv[t] = __floats2half2_rn(wv_g[2 * t], wv_g[2 * t + 1]);
    __syncthreads();

    const int tx = t & 31;
    const int ty = t >> 5;
    const int qb = ty << 2;

    float facc[4][2] = {};

#pragma unroll
    for (int grp = 0; grp < 8; grp++) {
        __half2 acc2[4][2];
#pragma unroll
        for (int i = 0; i < 4; i++) {
            acc2[i][0] = __floats2half2_rn(0.f, 0.f);
            acc2[i][1] = __floats2half2_rn(0.f, 0.f);
        }
#pragma unroll
        for (int u = 0; u < 4; u++) {
            const int hp = grp * 4 + u;
            const __half2 w2  = s_wv[hp];
            const __half2 k20 = s_kp[tx][hp];
            const __half2 k21 = s_kp[tx + 32][hp];
#pragma unroll
            for (int i = 0; i < 4; i++) {
                const __half2 q2 = s_qp[qb + i][hp];
                __half2 xa = __hadd2(q2, k20);
                __half2 xb = __hadd2(q2, k21);
                uint32_t ta = tanh2(*(uint32_t*)&xa);
                uint32_t tb = tanh2(*(uint32_t*)&xb);
                acc2[i][0] = __hfma2(w2, *(__half2*)&ta, acc2[i][0]);
                acc2[i][1] = __hfma2(w2, *(__half2*)&tb, acc2[i][1]);
            }
        }
#pragma unroll
        for (int i = 0; i < 4; i++) {
#pragma unroll
            for (int j = 0; j < 2; j++) {
                float2 f = __half22float2(acc2[i][j]);
                facc[i][j] += f.x + f.y;
            }
        }
    }

    float* out = g_sc + ((size_t)b * Qv + q0) * Kv + k0;
#pragma unroll
    for (int i = 0; i < 4; i++) {
        int q = qb + i;
        out[(size_t)q * Kv + tx]      = facc[i][0];
        out[(size_t)q * Kv + tx + 32] = facc[i][1];
    }
}

// ---------------------------------------------------------------------------
// Row softmax over K=1024; emits attn as bf16 hi/lo planes.
// ---------------------------------------------------------------------------
__global__ __launch_bounds__(256)
void softmax_kernel()
{
    const size_t row = (size_t)blockIdx.x * 1024;
    float* p = g_sc + row;
    const int t = threadIdx.x;

    float4 v = *(float4*)(p + (t << 2));
    float m = fmaxf(fmaxf(v.x, v.y), fmaxf(v.z, v.w));
#pragma unroll
    for (int o = 16; o; o >>= 1) m = fmaxf(m, __shfl_xor_sync(~0u, m, o));

    __shared__ float redm[8];
    __shared__ float reds[8];
    if ((t & 31) == 0) redm[t >> 5] = m;
    __syncthreads();
    float mall = redm[0];
#pragma unroll
    for (int w = 1; w < 8; w++) mall = fmaxf(mall, redm[w]);

    float e0 = __expf(v.x - mall);
    float e1 = __expf(v.y - mall);
    float e2 = __expf(v.z - mall);
    float e3 = __expf(v.w - mall);
    float s = e0 + e1 + e2 + e3;
#pragma unroll
    for (int o = 16; o; o >>= 1) s += __shfl_xor_sync(~0u, s, o);
    if ((t & 31) == 0) reds[t >> 5] = s;
    __syncthreads();
    float stot = reds[0];
#pragma unroll
    for (int w = 1; w < 8; w++) stot += reds[w];

    float inv = 1.0f / stot;
    float a0 = e0 * inv, a1 = e1 * inv, a2 = e2 * inv, a3 = e3 * inv;

    __nv_bfloat16 h0 = __float2bfloat16(a0), h1 = __float2bfloat16(a1);
    __nv_bfloat16 h2 = __float2bfloat16(a2), h3 = __float2bfloat16(a3);
    __nv_bfloat16 l0 = __float2bfloat16(a0 - __bfloat162float(h0));
    __nv_bfloat16 l1 = __float2bfloat16(a1 - __bfloat162float(h1));
    __nv_bfloat16 l2 = __float2bfloat16(a2 - __bfloat162float(h2));
    __nv_bfloat16 l3 = __float2bfloat16(a3 - __bfloat162float(h3));

    *(ushort4*)(g_ahi + row + (t << 2)) = make_ushort4(*(uint16_t*)&h0, *(uint16_t*)&h1, *(uint16_t*)&h2, *(uint16_t*)&h3);
    *(ushort4*)(g_alo + row + (t << 2)) = make_ushort4(*(uint16_t*)&l0, *(uint16_t*)&l1, *(uint16_t*)&l2, *(uint16_t*)&l3);
}

// ---------------------------------------------------------------------------
// AV GEMM: out[b] = attn[b] @ values[b], bf16x3 HMMA (m16n8k16).
// CTA tile 64(M) x 128(N), K-step 32, 4 warps, cp.async double buffer.
// ---------------------------------------------------------------------------
#define AS_ROW 40
#define BS_ROW 136
#define A_PLANE (64 * AS_ROW)
#define B_PLANE (32 * BS_ROW)
#define SMEM_A_BYTES (2 * 2 * A_PLANE * 2)
#define SMEM_B_BYTES (2 * 2 * B_PLANE * 2)
#define SMEM_TOTAL_AV (SMEM_A_BYTES + SMEM_B_BYTES)

__global__ __launch_bounds__(128)
void av_mma_kernel(float* __restrict__ Out)
{
    extern __shared__ char dyn[];
    const uint32_t sA = s2u(dyn);
    const uint32_t sB = s2u(dyn + SMEM_A_BYTES);

    const int t = threadIdx.x, wid = t >> 5, lane = t & 31;
    const int b = blockIdx.z;
    const int m0 = blockIdx.y * 64;
    const int n0 = blockIdx.x * 128;

    const __nv_bfloat16* Ah = g_ahi + ((size_t)b * 1024 + m0) * 1024;
    const __nv_bfloat16* Al = g_alo + ((size_t)b * 1024 + m0) * 1024;
    const __nv_bfloat16* Vh = g_vhi + (size_t)b * 1024 * 256 + n0;
    const __nv_bfloat16* Vl = g_vlo + (size_t)b * 1024 * 256 + n0;

    const int a_row = t >> 1, a_col = (t & 1) * 16;
    const int b_row = t >> 2, b_col = (t & 3) * 32;

    const int sub = lane >> 3, r8 = lane & 7;
    const uint32_t a_lane_off = (uint32_t)(((sub & 1) * 8 + r8) * (AS_ROW * 2) + (sub >> 1) * 16);
    const uint32_t b_lane_off = (uint32_t)(((sub & 1) * 8 + r8) * (BS_ROW * 2) + (sub >> 1) * 16);

    auto issue = [&](int step, int buf) {
        const size_t kb = (size_t)step * 32;
#pragma unroll
        for (int pl = 0; pl < 2; pl++) {
            const __nv_bfloat16* src = (pl ? Al : Ah) + (size_t)a_row * 1024 + kb + a_col;
            uint32_t d = sA + ((buf * 2 + pl) * A_PLANE + a_row * AS_ROW + a_col) * 2;
            cp16(d, src);
            cp16(d + 16, src + 8);
        }
#pragma unroll
        for (int pl = 0; pl < 2; pl++) {
            const __nv_bfloat16* src = (pl ? Vl : Vh) + (kb + b_row) * 256 + b_col;
            uint32_t d = sB + ((buf * 2 + pl) * B_PLANE + b_row * BS_ROW + b_col) * 2;
#pragma unroll
            for (int i = 0; i < 4; i++) cp16(d + 16 * i, src + 8 * i);
        }
    };

    float acc[4][4][4] = {};

    issue(0, 0);
    cp_commit();

    for (int s = 0; s < 32; s++) {
        const int buf = s & 1;
        if (s < 31) { issue(s + 1, buf ^ 1); cp_commit(); cp_wait<1>(); }
        else        { cp_wait<0>(); }
        __syncthreads();

#pragma unroll
        for (int k0 = 0; k0 < 32; k0 += 16) {
            uint32_t Af[2][4][4];
#pragma unroll
            for (int pl = 0; pl < 2; pl++)
#pragma unroll
                for (int mt = 0; mt < 4; mt++) {
                    uint32_t addr = sA + ((buf * 2 + pl) * A_PLANE + mt * 16 * AS_ROW + k0) * 2 + a_lane_off;
                    ldsm4(Af[pl][mt], addr);
                }
            uint32_t Bf[2][4][2];
#pragma unroll
            for (int pl = 0; pl < 2; pl++)
#pragma unroll
                for (int ntp = 0; ntp < 2; ntp++) {
                    uint32_t rr[4];
                    uint32_t addr = sB + ((buf * 2 + pl) * B_PLANE + k0 * BS_ROW) * 2
                                  + (uint32_t)(wid * 64 + ntp * 32) + b_lane_off;
                    ldsm4t(rr, addr);
                    Bf[pl][ntp * 2][0] = rr[0]; Bf[pl][ntp * 2][1] = rr[1];
                    Bf[pl][ntp * 2 + 1][0] = rr[2]; Bf[pl][ntp * 2 + 1][1] = rr[3];
                }
#pragma unroll
            for (int mt = 0; mt < 4; mt++)
#pragma unroll
                for (int nt = 0; nt < 4; nt++) {
                    mma_bf16(acc[mt][nt], Af[0][mt], Bf[0][nt]);
                    mma_bf16(acc[mt][nt], Af[0][mt], Bf[1][nt]);
                    mma_bf16(acc[mt][nt], Af[1][mt], Bf[0][nt]);
                }
        }
        __syncthreads();
    }

    const int g  = lane >> 2;
    const int tq = lane & 3;
    float* Ob = Out + (size_t)b * 1024 * 256;
#pragma unroll
    for (int mt = 0; mt < 4; mt++)
#pragma unroll
        for (int nt = 0; nt < 4; nt++) {
            int row = m0 + mt * 16 + g;
            int col = n0 + wid * 32 + nt * 8 + tq * 2;
            *(float2*)(Ob + (size_t)row * 256 + col)       = make_float2(acc[mt][nt][0], acc[mt][nt][1]);
            *(float2*)(Ob + (size_t)(row + 8) * 256 + col) = make_float2(acc[mt][nt][2], acc[mt][nt][3]);
        }
}

// ---------------------------------------------------------------------------
extern "C" void kernel_launch(void* const* d_in, const int* in_sizes, int n_in,
                              void* d_out, int out_size)
{
    (void)in_sizes; (void)n_in; (void)out_size;
    const float* queries = (const float*)d_in[0];
    const float* keys    = (const float*)d_in[1];
    const float* values  = (const float*)d_in[2];
    const float* W_q     = (const float*)d_in[3];
    const float* W_k     = (const float*)d_in[4];
    const float* w_v     = (const float*)d_in[5];
    float* out = (float*)d_out;

    cudaFuncSetAttribute(av_mma_kernel, cudaFuncAttributeMaxDynamicSharedMemorySize, SMEM_TOTAL_AV);

    // 1. fused projections (f16 out) + values bf16 split
    proj_vsplit_kernel<<<dim3(1, 256, 1), 256>>>(queries, keys, W_q, W_k, values);

    // 2. additive-tanh scores (f16x2 MUFU path)
    scores_kernel<<<dim3(Kv / 64, Qv / 32, Bv), 256>>>(w_v);

    // 3. softmax -> bf16 hi/lo attn planes
    softmax_kernel<<<Bv * Qv, 256>>>();

    // 4. out = attn @ values via bf16x3 HMMA
    av_mma_kernel<<<dim3(DVv / 128, Qv / 64, Bv), 128, SMEM_TOTAL_AV>>>(out);
}